// round 14
// baseline (speedup 1.0000x reference)
#include <cuda_runtime.h>

#define N_BOX    1024
#define N_CLS    80
#define MAX_OUT  100
#define THREADS  256
#define SLOTS    4          // N_BOX / THREADS
#define INF64    0xFFFFFFFFFFFFFFFFull
#define INF32    0xFFFFFFFFu

__device__ int g_res[N_CLS * MAX_OUT];
__device__ int g_cnt[N_CLS];
__device__ int g_done;   // zero at load; block 0 resets each launch

// SORT-FREE NMS: the per-iteration min-reduction over composite keys
// (~score_bits, idx) IS the sort. Pick = live item with max score (idx
// tie-break); it suppresses all live others with IOU > 0.5 — exactly the
// reference's sorted greedy, since every live item is later in order.
__global__ __launch_bounds__(THREADS) void nms_fused(
    const float4* __restrict__ boxes,   // [N_BOX] (y1,x1,y2,x2)
    const float*  __restrict__ scores,  // [N_CLS, N_BOX]
    float*        __restrict__ out,     // float32 output
    int out_size)
{
    const int c   = blockIdx.x;
    const int tid = threadIdx.x;

    __shared__ float4 b4s[N_BOX];
    __shared__ float  ars[N_BOX];
    __shared__ int    res_s[MAX_OUT];
    __shared__ unsigned long long s_next[3];   // rotating winner slots

    // Zero this block's slice of the output (block 0 scatters strictly after
    // all blocks arrive; ordering covered by fence + arrival counter).
    for (int i = c * THREADS + tid; i < out_size; i += N_CLS * THREADS)
        out[i] = 0.0f;

    // ---- setup: boxes+areas -> smem; keys + liveness -> registers ----
    const float* sc = scores + (size_t)c * N_BOX;
    unsigned int hi[SLOTS];     // ~score_bits: ascending == score descending
    unsigned int live = 0;      // 4-bit liveness mask, register-resident
#pragma unroll
    for (int s = 0; s < SLOTS; ++s) {
        int t = tid + s * THREADS;
        float  sv = sc[t];
        float4 b  = boxes[t];                  // (y1,x1,y2,x2)
        b4s[t] = b;
        ars[t] = __fmul_rn(__fsub_rn(b.z, b.x), __fsub_rn(b.w, b.y));
        hi[s]  = ~__float_as_uint(sv);         // non-negative: bit-monotone
        if (sv > 0.5f) live |= 1u << s;
    }
    if (tid == 0) { s_next[0] = INF64; s_next[1] = INF64; s_next[2] = INF64; }
    __syncthreads();

    // ---- greedy: ONE barrier per kept item, liveness in registers ----
    int rank = 0;
    int slot = 0;
    while (true) {
        // Per-thread best (min) key among live slots. Ascending s scan with
        // strict '<' => smallest j wins thread-local ties automatically.
        unsigned int bh = INF32, bj = INF32;
#pragma unroll
        for (int s = 0; s < SLOTS; ++s) {
            if ((live >> s) & 1u) {
                if (hi[s] < bh) { bh = hi[s]; bj = (unsigned)(tid + s * THREADS); }
            }
        }
        // 2-stage 32-bit warp reduction: min score-key, then min idx on ties.
        unsigned int u = __reduce_min_sync(0xFFFFFFFFu, bh);
        unsigned int v = __reduce_min_sync(0xFFFFFFFFu, (bh == u) ? bj : INF32);
        if ((tid & 31) == 0 && u != INF32)
            atomicMin(&s_next[slot], ((unsigned long long)u << 32) | v);
        // Reset the slot used NEXT iteration: its last readers finished
        // before barrier(it-1), its next atomics start after barrier(it):
        // this pre-barrier write is ordered on both sides.
        {
            int ns = slot + 1; if (ns == 3) ns = 0;
            if (tid == 0) s_next[ns] = INF64;
        }
        __syncthreads();

        unsigned long long k = s_next[slot];
        if (++slot == 3) slot = 0;
        if (k == INF64) break;                 // no live candidates remain
        const int idx = (int)(k & 0xFFFFFFFFull);   // original box index
        if (tid == 0) res_s[rank] = idx;
        ++rank;
        if (rank >= MAX_OUT) break;            // rank >= 100 is discarded

        // Suppress all live items against the picked box (all are later in
        // sorted order by construction). Exact-rounding ops mirror XLA.
        const float4 bi = b4s[idx];
        const float  ai = ars[idx];
#pragma unroll
        for (int s = 0; s < SLOTS; ++s) {
            if ((live >> s) & 1u) {
                int j = tid + s * THREADS;
                if (j == idx) { live &= ~(1u << s); continue; }
                float4 bj4 = b4s[j];
                float ih = fmaxf(__fsub_rn(fminf(bi.z, bj4.z),
                                           fmaxf(bi.x, bj4.x)), 0.0f);
                float iw = fmaxf(__fsub_rn(fminf(bi.w, bj4.w),
                                           fmaxf(bi.y, bj4.y)), 0.0f);
                float inter = __fmul_rn(ih, iw);
                float uni   = __fsub_rn(__fadd_rn(ai, ars[j]), inter);
                // NaN (0/0) > 0.5 is false, matching the reference.
                if (__fdiv_rn(inter, uni) > 0.5f) live &= ~(1u << s);
            }
        }
    }
    __syncthreads();

    // ---- publish per-class results; release; arrive ----
    for (int t = tid; t < rank; t += THREADS)
        g_res[c * MAX_OUT + t] = res_s[t];
    if (tid == 0) g_cnt[c] = rank;
    __threadfence();
    __syncthreads();
    if (tid == 0) atomicAdd(&g_done, 1);

    // ---- block 0: wait for all classes, scatter compacted float rows ----
    if (c == 0) {
        if (tid == 0) {
            while (atomicAdd(&g_done, 0) < N_CLS) __nanosleep(100);
        }
        __syncthreads();
        __threadfence();   // acquire before reading g_res/g_cnt

        __shared__ int s_cnt[N_CLS];
        __shared__ int offs[N_CLS];
        if (tid < N_CLS) s_cnt[tid] = g_cnt[tid];   // parallel loads
        __syncthreads();
        if (tid == 0) {
            int acc = 0;
            #pragma unroll 8
            for (int cc = 0; cc < N_CLS; ++cc) { offs[cc] = acc; acc += s_cnt[cc]; }
        }
        __syncthreads();

        for (int e = tid; e < N_CLS * MAX_OUT; e += THREADS) {
            int cc = e / MAX_OUT;
            int k  = e - cc * MAX_OUT;
            if (k < s_cnt[cc]) {
                int p = offs[cc] + k;
                out[3 * p + 0] = 0.0f;            // batch index (B == 1)
                out[3 * p + 1] = (float)cc;
                out[3 * p + 2] = (float)g_res[e];
            }
        }
        __syncthreads();
        if (tid == 0) { __threadfence(); g_done = 0; }   // reset for replay
    }
}

extern "C" void kernel_launch(void* const* d_in, const int* in_sizes, int n_in,
                              void* d_out, int out_size)
{
    const float* boxes  = (const float*)d_in[0];
    const float* scores = (const float*)(n_in > 1 ? d_in[1] : d_in[0]);
    if (n_in > 1 && in_sizes[0] > in_sizes[1]) {   // clearly reversed
        const float* t = boxes; boxes = scores; scores = t;
    }

    nms_fused<<<N_CLS, THREADS>>>((const float4*)boxes, scores,
                                  (float*)d_out, out_size);
}

// round 15
// speedup vs baseline: 2.0737x; 2.0737x over previous
#include <cuda_runtime.h>

#define N_BOX    1024
#define N_CLS    80
#define MAX_OUT  100
#define THREADS  512
#define KB       32     // greedy batch size

__device__ int g_res[N_CLS * MAX_OUT];
__device__ int g_cnt[N_CLS];
__device__ int g_done;   // zero at load; block 0 resets each launch

// Exact-rounding IOU > 0.5 test (mirrors XLA's single-rounded ops; NaN(0/0)
// compares false, like the reference).
__device__ __forceinline__ bool iou_gt(const float4 a, float aa,
                                       const float4 b, float ab)
{
    float ih = fmaxf(__fsub_rn(fminf(a.z, b.z), fmaxf(a.x, b.x)), 0.0f);
    float iw = fmaxf(__fsub_rn(fminf(a.w, b.w), fmaxf(a.y, b.y)), 0.0f);
    float inter = __fmul_rn(ih, iw);
    float uni   = __fsub_rn(__fadd_rn(aa, ab), inter);
    return __fdiv_rn(inter, uni) > 0.5f;
}

__global__ __launch_bounds__(THREADS) void nms_fused(
    const float4* __restrict__ boxes,   // [N_BOX] (y1,x1,y2,x2)
    const float*  __restrict__ scores,  // [N_CLS, N_BOX]
    float*        __restrict__ out,     // float32 output
    int out_size)
{
    const int c   = blockIdx.x;
    const int tid = threadIdx.x;

    __shared__ unsigned long long keys[N_BOX];
    __shared__ float4 b4s[N_BOX];
    __shared__ float  ars[N_BOX];
    __shared__ unsigned char keepb[N_BOX];
    __shared__ int    res_s[MAX_OUT];
    __shared__ int    s_cut;
    __shared__ int    batch_pos[KB];
    __shared__ float4 batch_b4[KB];
    __shared__ float  batch_ar[KB];
    __shared__ unsigned int cols[KB];    // cols[m]: earlier batch conflicts
    __shared__ int    s_nb, s_cur;

    // Zero this block's slice of the output (block 0 scatters strictly after
    // all blocks arrive; ordering covered by fence + arrival counter).
    for (int i = c * THREADS + tid; i < out_size; i += N_CLS * THREADS)
        out[i] = 0.0f;

    // ---- composite keys: ascending == (score desc, index asc) ----
    const float* sc = scores + (size_t)c * N_BOX;
    for (int t = tid; t < N_BOX; t += THREADS) {
        unsigned int bits = __float_as_uint(sc[t]);
        keys[t] = ((unsigned long long)(~bits) << 32) | (unsigned int)t;
    }
    if (tid == 0) s_cut = 0;
    __syncthreads();

    // ---- bitonic sort ascending (keys unique: index in low bits) ----
    for (int k = 2; k <= N_BOX; k <<= 1) {
        for (int j = k >> 1; j > 0; j >>= 1) {
            for (int t = tid; t < N_BOX; t += THREADS) {
                int ixj = t ^ j;
                if (ixj > t) {
                    bool up = ((t & k) == 0);
                    unsigned long long a = keys[t], b = keys[ixj];
                    if ((a > b) == up) { keys[t] = b; keys[ixj] = a; }
                }
            }
            __syncthreads();
        }
    }

    // ---- cutoff = #scores > 0.5 (a prefix of the sorted order) ----
    for (int t = tid; t < N_BOX; t += THREADS) {
        float s  = __uint_as_float(~(unsigned int)(keys[t] >> 32));
        bool kt  = (s > 0.5f);
        bool kt1 = false;
        if (t < N_BOX - 1) {
            float s1 = __uint_as_float(~(unsigned int)(keys[t + 1] >> 32));
            kt1 = (s1 > 0.5f);
        }
        if (kt && !kt1) s_cut = t + 1;
        if (t == N_BOX - 1 && kt) s_cut = N_BOX;
    }
    __syncthreads();
    const int cutoff = s_cut;

    // ---- gather boxes (sorted order); prefix starts live ----
    for (int t = tid; t < cutoff; t += THREADS) {
        int o = (int)(keys[t] & 0xFFFFFFFFull);
        float4 b = boxes[o];
        b4s[t] = b;
        ars[t] = __fmul_rn(__fsub_rn(b.z, b.x), __fsub_rn(b.w, b.y));
        keepb[t] = 1;
    }
    __syncthreads();

    // ==== BATCHED greedy: each round processes the next <=KB consecutive
    // live items. Greedy's next picks come only from this batch (everything
    // after is lower priority, everything between is dead), and validity
    // within the batch is exactly mini-greedy on the conflict matrix. ====
    int rank = 0;
    int cur  = 0;
    while (rank < MAX_OUT) {
        // -- selection: next <=KB live items from the cursor (thread 0) --
        if (tid == 0) {
            int nb = 0, p = cur;
            while (nb < KB && p < cutoff) {
                if (keepb[p]) batch_pos[nb++] = p;
                ++p;
            }
            s_nb = nb; s_cur = p;
        }
        __syncthreads();
        const int nb = s_nb;
        if (nb == 0) break;
        cur = s_cur;                       // == last batch position + 1

        if (tid < nb) {
            int p = batch_pos[tid];
            batch_b4[tid] = b4s[p];
            batch_ar[tid] = ars[p];
        }
        if (tid < KB) cols[tid] = 0;
        __syncthreads();

        // -- in-batch pair conflicts, one pair per thread (independent) --
        const int npairs = nb * (nb - 1) / 2;
        for (int t = tid; t < npairs; t += THREADS) {
            int m = 1;
            while (m * (m + 1) / 2 <= t) ++m;     // decode (l < m) from t
            int l = t - m * (m - 1) / 2;
            if (iou_gt(batch_b4[l], batch_ar[l], batch_b4[m], batch_ar[m]))
                atomicOr(&cols[m], 1u << l);
        }
        __syncthreads();

        // -- resolve validity: m valid iff no VALID earlier conflict.
        //    Uniform (reads only smem cols); done redundantly, zero comms. --
        unsigned int valid = 0;
        for (int m = 0; m < nb; ++m)
            if ((cols[m] & valid) == 0) valid |= 1u << m;

        if (tid == 0) {
            int r = rank;
            for (int m = 0; m < nb && r < MAX_OUT; ++m)
                if ((valid >> m) & 1u)
                    res_s[r++] = (int)(keys[batch_pos[m]] & 0xFFFFFFFFull);
        }
        rank += __popc(valid);                    // uniform
        if (rank >= MAX_OUT) { rank = MAX_OUT; break; }

        // -- wide suppression: every remaining live j vs all valid members --
        for (int j = cur + tid; j < cutoff; j += THREADS) {
            if (keepb[j]) {
                float4 bj = b4s[j];
                float  aj = ars[j];
                bool kill = false;
                for (int m = 0; m < nb; ++m)
                    if ((valid >> m) & 1u)
                        kill |= iou_gt(batch_b4[m], batch_ar[m], bj, aj);
                if (kill) keepb[j] = 0;
            }
        }
        __syncthreads();
    }
    __syncthreads();   // res_s (thread 0 writes) visible to all

    // ---- publish per-class results; release; arrive ----
    for (int t = tid; t < rank; t += THREADS)
        g_res[c * MAX_OUT + t] = res_s[t];
    if (tid == 0) g_cnt[c] = rank;
    __threadfence();
    __syncthreads();
    if (tid == 0) atomicAdd(&g_done, 1);

    // ---- block 0: wait for all classes, scatter compacted float rows ----
    if (c == 0) {
        if (tid == 0) {
            while (atomicAdd(&g_done, 0) < N_CLS) __nanosleep(100);
        }
        __syncthreads();
        __threadfence();   // acquire before reading g_res/g_cnt

        __shared__ int s_cnt[N_CLS];
        __shared__ int offs[N_CLS];
        if (tid < N_CLS) s_cnt[tid] = g_cnt[tid];   // parallel loads
        __syncthreads();
        if (tid == 0) {
            int acc = 0;
            #pragma unroll 8
            for (int cc = 0; cc < N_CLS; ++cc) { offs[cc] = acc; acc += s_cnt[cc]; }
        }
        __syncthreads();

        for (int e = tid; e < N_CLS * MAX_OUT; e += THREADS) {
            int cc = e / MAX_OUT;
            int k  = e - cc * MAX_OUT;
            if (k < s_cnt[cc]) {
                int p = offs[cc] + k;
                out[3 * p + 0] = 0.0f;            // batch index (B == 1)
                out[3 * p + 1] = (float)cc;
                out[3 * p + 2] = (float)g_res[e];
            }
        }
        __syncthreads();
        if (tid == 0) { __threadfence(); g_done = 0; }   // reset for replay
    }
}

extern "C" void kernel_launch(void* const* d_in, const int* in_sizes, int n_in,
                              void* d_out, int out_size)
{
    const float* boxes  = (const float*)d_in[0];
    const float* scores = (const float*)(n_in > 1 ? d_in[1] : d_in[0]);
    if (n_in > 1 && in_sizes[0] > in_sizes[1]) {   // clearly reversed
        const float* t = boxes; boxes = scores; scores = t;
    }

    nms_fused<<<N_CLS, THREADS>>>((const float4*)boxes, scores,
                                  (float*)d_out, out_size);
}

// round 16
// speedup vs baseline: 2.6087x; 1.2580x over previous
#include <cuda_runtime.h>

#define N_BOX    1024
#define N_CLS    80
#define MAX_OUT  100
#define THREADS  1024
#define KB       64     // greedy batch size

__device__ int g_res[N_CLS * MAX_OUT];
__device__ int g_cnt[N_CLS];
__device__ int g_done;   // zero at load; block 0 resets each launch

// Exact-rounding IOU > 0.5 (mirrors XLA single-rounded ops; NaN(0/0) -> false).
// Call with the EARLIER-in-order box first (matches reference add order).
__device__ __forceinline__ bool iou_gt(const float4 a, float aa,
                                       const float4 b, float ab)
{
    float ih = fmaxf(__fsub_rn(fminf(a.z, b.z), fmaxf(a.x, b.x)), 0.0f);
    float iw = fmaxf(__fsub_rn(fminf(a.w, b.w), fmaxf(a.y, b.y)), 0.0f);
    float inter = __fmul_rn(ih, iw);
    float uni   = __fsub_rn(__fadd_rn(aa, ab), inter);
    return __fdiv_rn(inter, uni) > 0.5f;
}

__global__ __launch_bounds__(THREADS) void nms_fused(
    const float4* __restrict__ boxes,   // [N_BOX] (y1,x1,y2,x2)
    const float*  __restrict__ scores,  // [N_CLS, N_BOX]
    float*        __restrict__ out,     // float32 output
    int out_size)
{
    const int c   = blockIdx.x;
    const int tid = threadIdx.x;

    __shared__ unsigned long long keys[N_BOX];
    __shared__ float4 b4s[N_BOX];
    __shared__ float  ars[N_BOX];
    __shared__ unsigned int lw[32];          // live bitmap over sorted positions
    __shared__ int    res_s[MAX_OUT];
    __shared__ float4 batch_b4[KB];
    __shared__ float  batch_ar[KB];
    __shared__ int    batch_idx[KB];
    __shared__ unsigned long long cols[KB];  // earlier-in-batch conflicts
    __shared__ int    s_cut;

    // Zero this block's slice of the output (block 0 scatters strictly after
    // all blocks arrive; ordering covered by fence + arrival counter).
    for (int i = c * THREADS + tid; i < out_size; i += N_CLS * THREADS)
        out[i] = 0.0f;

    // ---- composite key in REGISTER: ascending == (score desc, idx asc) ----
    const float* sc = scores + (size_t)c * N_BOX;
    float sv = sc[tid];
    unsigned long long key =
        ((unsigned long long)(~__float_as_uint(sv)) << 32) | (unsigned)tid;
    if (tid == 0) s_cut = 0;

    // ---- hybrid bitonic sort: shfl for j<32 (no barriers), smem for j>=32 --
    for (int k = 2; k <= 32; k <<= 1) {               // fully intra-warp
        const bool up = ((tid & k) == 0);
        for (int j = k >> 1; j >= 1; j >>= 1) {
            unsigned long long other = __shfl_xor_sync(0xFFFFFFFFu, key, j);
            bool lower = ((tid & j) == 0);
            unsigned long long mn = (key < other) ? key : other;
            unsigned long long mx = (key < other) ? other : key;
            key = (lower == up) ? mn : mx;
        }
    }
    for (int k = 64; k <= N_BOX; k <<= 1) {
        const bool up = ((tid & k) == 0);
        int j = k >> 1;
        for (; j >= 32; j >>= 1) {                    // cross-warp via smem
            keys[tid] = key;
            __syncthreads();
            unsigned long long other = keys[tid ^ j];
            bool lower = ((tid & j) == 0);
            unsigned long long mn = (key < other) ? key : other;
            unsigned long long mx = (key < other) ? other : key;
            key = (lower == up) ? mn : mx;
            __syncthreads();
        }
        for (; j >= 1; j >>= 1) {                     // tail intra-warp
            unsigned long long other = __shfl_xor_sync(0xFFFFFFFFu, key, j);
            bool lower = ((tid & j) == 0);
            unsigned long long mn = (key < other) ? key : other;
            unsigned long long mx = (key < other) ? other : key;
            key = (lower == up) ? mn : mx;
        }
    }
    keys[tid] = key;
    __syncthreads();

    // ---- cutoff = #scores > 0.5 (sorted prefix; unique boundary writer) ----
    {
        float s = __uint_as_float(~(unsigned int)(keys[tid] >> 32));
        bool kt = (s > 0.5f), kt1 = false;
        if (tid < N_BOX - 1) {
            float s1 = __uint_as_float(~(unsigned int)(keys[tid + 1] >> 32));
            kt1 = (s1 > 0.5f);
        }
        if (kt && !kt1) s_cut = tid + 1;
    }
    __syncthreads();
    const int cutoff = s_cut;

    // ---- gather boxes (sorted order); init live bitmap = prefix ----
    if (tid < cutoff) {
        int o = (int)(keys[tid] & 0xFFFFFFFFull);
        float4 b = boxes[o];
        b4s[tid] = b;
        ars[tid] = __fmul_rn(__fsub_rn(b.z, b.x), __fsub_rn(b.w, b.y));
    }
    if (tid < 32) {
        int base = tid << 5;
        unsigned int w = 0;
        if (cutoff >= base + 32)     w = 0xFFFFFFFFu;
        else if (cutoff > base)      w = (1u << (cutoff - base)) - 1u;
        lw[tid] = w;
    }
    __syncthreads();

    // ==== batched greedy: each round = next <=KB consecutive LIVE items.
    // Greedy's next picks come only from this batch; in-batch validity is
    // exact mini-greedy on the conflict matrix. ~2 rounds to 100 kept. ====
    int rank = 0, cur = 0;
    while (rank < MAX_OUT) {
        // -- UNIFORM selection scan over the bitmap (all threads identical) --
        int nb = 0, mypos = -1, last = -1;
        {
            int w = cur >> 5;
            unsigned int word = (w < 32) ? (lw[w] & (0xFFFFFFFFu << (cur & 31)))
                                         : 0u;
            while (nb < KB) {
                while (word == 0u) {
                    if (++w >= 32) break;
                    word = lw[w];
                }
                if (w >= 32) break;
                int b = __ffs(word) - 1;
                word &= word - 1u;
                int pos = (w << 5) + b;
                if (nb == tid) mypos = pos;
                last = pos;
                ++nb;
            }
        }
        if (nb == 0) break;
        cur = last + 1;

        if (tid < KB) cols[tid] = 0ull;
        if (mypos >= 0) {                       // tid < nb
            batch_b4[tid]  = b4s[mypos];
            batch_ar[tid]  = ars[mypos];
            batch_idx[tid] = (int)(keys[mypos] & 0xFFFFFFFFull);
        }
        __syncthreads();

        // -- in-batch pair conflicts (independent, ~2 pairs/thread) --
        const int npairs = nb * (nb - 1) / 2;
        for (int t = tid; t < npairs; t += THREADS) {
            int m = (int)((1.0f + sqrtf(1.0f + 8.0f * (float)t)) * 0.5f);
            while (m * (m - 1) / 2 > t) --m;          // fix float error
            while ((m + 1) * m / 2 <= t) ++m;
            int l = t - m * (m - 1) / 2;              // l < m
            if (iou_gt(batch_b4[l], batch_ar[l], batch_b4[m], batch_ar[m]))
                atomicOr(&cols[m], 1ull << l);
        }
        __syncthreads();

        // -- validity: m valid iff no valid earlier conflict (uniform) --
        unsigned long long valid = 0ull;
        for (int m = 0; m < nb; ++m)
            if ((cols[m] & valid) == 0ull) valid |= 1ull << m;

        // -- parallel emission: slot = rank + popc(valid below me) --
        if (tid < nb && ((valid >> tid) & 1ull)) {
            int slot = rank + __popcll(valid & ((1ull << tid) - 1ull));
            if (slot < MAX_OUT) res_s[slot] = batch_idx[tid];
        }
        rank += (int)__popcll(valid);
        if (rank >= MAX_OUT) { rank = MAX_OUT; break; }

        // -- suppression: one position per thread against valid members --
        if (tid >= cur && tid < cutoff &&
            ((lw[tid >> 5] >> (tid & 31)) & 1u)) {
            float4 bj = b4s[tid];
            float  aj = ars[tid];
            bool kill = false;
            unsigned long long v = valid;
            while (v) {
                int m = __ffsll(v) - 1;
                v &= v - 1ull;
                kill |= iou_gt(batch_b4[m], batch_ar[m], bj, aj);
            }
            if (kill) atomicAnd(&lw[tid >> 5], ~(1u << (tid & 31)));
        }
        __syncthreads();
    }
    __syncthreads();   // res_s visible to all

    // ---- publish per-class results; release; arrive ----
    if (tid < rank) g_res[c * MAX_OUT + tid] = res_s[tid];
    if (tid == 0) g_cnt[c] = rank;
    __threadfence();
    __syncthreads();
    if (tid == 0) atomicAdd(&g_done, 1);

    // ---- block 0: wait for all classes, scatter compacted float rows ----
    if (c == 0) {
        if (tid == 0) {
            while (atomicAdd(&g_done, 0) < N_CLS) __nanosleep(100);
        }
        __syncthreads();
        __threadfence();   // acquire before reading g_res/g_cnt

        __shared__ int s_cnt[N_CLS];
        __shared__ int offs[N_CLS];
        if (tid < N_CLS) s_cnt[tid] = g_cnt[tid];   // parallel loads
        __syncthreads();
        if (tid == 0) {
            int acc = 0;
            #pragma unroll 8
            for (int cc = 0; cc < N_CLS; ++cc) { offs[cc] = acc; acc += s_cnt[cc]; }
        }
        __syncthreads();

        for (int e = tid; e < N_CLS * MAX_OUT; e += THREADS) {
            int cc = e / MAX_OUT;
            int k  = e - cc * MAX_OUT;
            if (k < s_cnt[cc]) {
                int p = offs[cc] + k;
                out[3 * p + 0] = 0.0f;            // batch index (B == 1)
                out[3 * p + 1] = (float)cc;
                out[3 * p + 2] = (float)g_res[e];
            }
        }
        __syncthreads();
        if (tid == 0) { __threadfence(); g_done = 0; }   // reset for replay
    }
}

extern "C" void kernel_launch(void* const* d_in, const int* in_sizes, int n_in,
                              void* d_out, int out_size)
{
    const float* boxes  = (const float*)d_in[0];
    const float* scores = (const float*)(n_in > 1 ? d_in[1] : d_in[0]);
    if (n_in > 1 && in_sizes[0] > in_sizes[1]) {   // clearly reversed
        const float* t = boxes; boxes = scores; scores = t;
    }

    nms_fused<<<N_CLS, THREADS>>>((const float4*)boxes, scores,
                                  (float*)d_out, out_size);
}

// round 17
// speedup vs baseline: 3.5212x; 1.3498x over previous
#include <cuda_runtime.h>

#define N_BOX    1024
#define N_CLS    80
#define MAX_OUT  100
#define THREADS  1024
#define KB       64     // greedy batch size

__device__ int g_res[N_CLS * MAX_OUT];
__device__ int g_cnt[N_CLS];
__device__ int g_done;   // zero at load; block 0 resets each launch

// Exact-rounding IOU > 0.5 (mirrors XLA single-rounded ops; NaN(0/0) -> false).
// Call with the EARLIER-in-order box first (matches reference add order).
__device__ __forceinline__ bool iou_gt(const float4 a, float aa,
                                       const float4 b, float ab)
{
    float ih = fmaxf(__fsub_rn(fminf(a.z, b.z), fmaxf(a.x, b.x)), 0.0f);
    float iw = fmaxf(__fsub_rn(fminf(a.w, b.w), fmaxf(a.y, b.y)), 0.0f);
    float inter = __fmul_rn(ih, iw);
    float uni   = __fsub_rn(__fadd_rn(aa, ab), inter);
    return __fdiv_rn(inter, uni) > 0.5f;
}

__global__ __launch_bounds__(THREADS) void nms_fused(
    const float4* __restrict__ boxes,   // [N_BOX] (y1,x1,y2,x2)
    const float*  __restrict__ scores,  // [N_CLS, N_BOX]
    float*        __restrict__ out,     // float32 output
    int out_size)
{
    const int c   = blockIdx.x;
    const int tid = threadIdx.x;

    __shared__ unsigned long long keys[N_BOX];
    __shared__ float4 b4s[N_BOX];
    __shared__ float  ars[N_BOX];
    __shared__ unsigned int lw[32];          // live bitmap over sorted positions
    __shared__ int    wpre[32];              // exclusive prefix of word popcounts
    __shared__ int    s_total;
    __shared__ int    res_s[MAX_OUT];
    __shared__ float4 batch_b4[KB];
    __shared__ float  batch_ar[KB];
    __shared__ int    batch_idx[KB];
    __shared__ unsigned long long cols[KB];  // earlier-in-batch conflicts
    __shared__ unsigned long long s_valid;

    // Zero this block's slice of the output (block 0 scatters strictly after
    // all blocks arrive; ordering covered by fence + arrival counter).
    for (int i = c * THREADS + tid; i < out_size; i += N_CLS * THREADS)
        out[i] = 0.0f;

    // ---- composite key in REGISTER: ascending == (score desc, idx asc) ----
    const float* sc = scores + (size_t)c * N_BOX;
    float sv = sc[tid];
    unsigned long long key =
        ((unsigned long long)(~__float_as_uint(sv)) << 32) | (unsigned)tid;

    // ---- hybrid bitonic sort: shfl for j<32 (no barriers), smem for j>=32 --
    for (int k = 2; k <= 32; k <<= 1) {               // fully intra-warp
        const bool up = ((tid & k) == 0);
        for (int j = k >> 1; j >= 1; j >>= 1) {
            unsigned long long other = __shfl_xor_sync(0xFFFFFFFFu, key, j);
            bool lower = ((tid & j) == 0);
            unsigned long long mn = (key < other) ? key : other;
            unsigned long long mx = (key < other) ? other : key;
            key = (lower == up) ? mn : mx;
        }
    }
    for (int k = 64; k <= N_BOX; k <<= 1) {
        const bool up = ((tid & k) == 0);
        int j = k >> 1;
        for (; j >= 32; j >>= 1) {                    // cross-warp via smem
            keys[tid] = key;
            __syncthreads();
            unsigned long long other = keys[tid ^ j];
            bool lower = ((tid & j) == 0);
            unsigned long long mn = (key < other) ? key : other;
            unsigned long long mx = (key < other) ? other : key;
            key = (lower == up) ? mn : mx;
            __syncthreads();
        }
        for (; j >= 1; j >>= 1) {                     // tail intra-warp
            unsigned long long other = __shfl_xor_sync(0xFFFFFFFFu, key, j);
            bool lower = ((tid & j) == 0);
            unsigned long long mn = (key < other) ? key : other;
            unsigned long long mx = (key < other) ? other : key;
            key = (lower == up) ? mn : mx;
        }
    }
    keys[tid] = key;

    // ---- live bits = (score > 0.5) via per-warp ballot; gather live boxes --
    {
        float s = __uint_as_float(~(unsigned int)(key >> 32));
        bool pred = (s > 0.5f);
        unsigned int ball = __ballot_sync(0xFFFFFFFFu, pred);
        if ((tid & 31) == 0) lw[tid >> 5] = ball;
        if (pred) {
            int o = (int)(key & 0xFFFFFFFFull);
            float4 b = boxes[o];
            b4s[tid] = b;
            ars[tid] = __fmul_rn(__fsub_rn(b.z, b.x), __fsub_rn(b.w, b.y));
        }
    }
    __syncthreads();

    // ==== batched greedy: each round = first <=KB live items (they are the
    // next consecutive live run in sorted order; greedy's next picks come
    // only from them; in-batch validity = exact mini-greedy). ====
    int rank = 0;
    while (rank < MAX_OUT) {
        // -- A: warp 0 scans word popcounts; others zero cols --
        if (tid < 32) {
            int pc = __popc(lw[tid]);
            int inc = pc;
            #pragma unroll
            for (int d = 1; d < 32; d <<= 1) {
                int n = __shfl_up_sync(0xFFFFFFFFu, inc, d);
                if (tid >= d) inc += n;
            }
            wpre[tid] = inc - pc;                  // exclusive prefix
            if (tid == 31) s_total = inc;
        }
        if (tid >= 64 && tid < 64 + KB) cols[tid - 64] = 0ull;
        __syncthreads();

        int nb = s_total; if (nb > KB) nb = KB;
        if (nb == 0) break;

        // -- rank-based batch membership (O(10) per thread, read-only) --
        const unsigned int myw = lw[tid >> 5];
        const bool amlive = ((myw >> (tid & 31)) & 1u) != 0u;
        int myrank = -1;
        if (amlive) {
            int r = wpre[tid >> 5] + __popc(myw & ((1u << (tid & 31)) - 1u));
            if (r < nb) {
                myrank = r;
                batch_b4[r]  = b4s[tid];
                batch_ar[r]  = ars[tid];
                batch_idx[r] = (int)(key & 0xFFFFFFFFull);
            }
        }
        __syncthreads();

        // -- in-batch pair conflicts (independent, ~2 pairs/thread) --
        const int npairs = nb * (nb - 1) / 2;
        for (int t = tid; t < npairs; t += THREADS) {
            int m = (int)((1.0f + sqrtf(1.0f + 8.0f * (float)t)) * 0.5f);
            while (m * (m - 1) / 2 > t) --m;          // fix float error
            while ((m + 1) * m / 2 <= t) ++m;
            int l = t - m * (m - 1) / 2;              // l < m
            if (iou_gt(batch_b4[l], batch_ar[l], batch_b4[m], batch_ar[m]))
                atomicOr(&cols[m], 1ull << l);
        }
        __syncthreads();

        // -- validity on thread 0 only (latency, not 1024 redundant copies) --
        if (tid == 0) {
            unsigned long long valid = 0ull;
            for (int m = 0; m < nb; ++m)
                if ((cols[m] & valid) == 0ull) valid |= 1ull << m;
            s_valid = valid;
        }
        __syncthreads();
        const unsigned long long valid = s_valid;

        // -- parallel emission: slot = rank + popc(valid below my rank) --
        if (myrank >= 0 && ((valid >> myrank) & 1ull)) {
            int slot = rank + __popcll(valid & ((1ull << myrank) - 1ull));
            if (slot < MAX_OUT) res_s[slot] = batch_idx[myrank];
        }
        rank += (int)__popcll(valid);
        if (rank >= MAX_OUT) { rank = MAX_OUT; break; }

        // -- suppression + bit clears (each thread owns exactly its bit):
        //    batch members always clear (selected or in-batch-suppressed);
        //    others test valid members in order with EARLY EXIT. --
        if (amlive) {
            bool clear = true;
            if (myrank < 0) {
                float4 bj = b4s[tid];
                float  aj = ars[tid];
                clear = false;
                unsigned long long v = valid;
                while (v) {
                    int m = __ffsll((long long)v) - 1;
                    v &= v - 1ull;
                    if (iou_gt(batch_b4[m], batch_ar[m], bj, aj)) {
                        clear = true; break;
                    }
                }
            }
            if (clear) atomicAnd(&lw[tid >> 5], ~(1u << (tid & 31)));
        }
        __syncthreads();
    }
    __syncthreads();   // res_s visible to all

    // ---- publish per-class results; release; arrive ----
    if (tid < rank) g_res[c * MAX_OUT + tid] = res_s[tid];
    if (tid == 0) g_cnt[c] = rank;
    __threadfence();
    __syncthreads();
    if (tid == 0) atomicAdd(&g_done, 1);

    // ---- block 0: wait for all classes, scatter compacted float rows ----
    if (c == 0) {
        if (tid == 0) {
            while (atomicAdd(&g_done, 0) < N_CLS) __nanosleep(100);
        }
        __syncthreads();
        __threadfence();   // acquire before reading g_res/g_cnt

        __shared__ int s_cnt[N_CLS];
        __shared__ int offs[N_CLS];
        if (tid < N_CLS) s_cnt[tid] = g_cnt[tid];   // parallel loads
        __syncthreads();
        if (tid == 0) {
            int acc = 0;
            #pragma unroll 8
            for (int cc = 0; cc < N_CLS; ++cc) { offs[cc] = acc; acc += s_cnt[cc]; }
        }
        __syncthreads();

        for (int e = tid; e < N_CLS * MAX_OUT; e += THREADS) {
            int cc = e / MAX_OUT;
            int k  = e - cc * MAX_OUT;
            if (k < s_cnt[cc]) {
                int p = offs[cc] + k;
                out[3 * p + 0] = 0.0f;            // batch index (B == 1)
                out[3 * p + 1] = (float)cc;
                out[3 * p + 2] = (float)g_res[e];
            }
        }
        __syncthreads();
        if (tid == 0) { __threadfence(); g_done = 0; }   // reset for replay
    }
}

extern "C" void kernel_launch(void* const* d_in, const int* in_sizes, int n_in,
                              void* d_out, int out_size)
{
    const float* boxes  = (const float*)d_in[0];
    const float* scores = (const float*)(n_in > 1 ? d_in[1] : d_in[0]);
    if (n_in > 1 && in_sizes[0] > in_sizes[1]) {   // clearly reversed
        const float* t = boxes; boxes = scores; scores = t;
    }

    nms_fused<<<N_CLS, THREADS>>>((const float4*)boxes, scores,
                                  (float*)d_out, out_size);
}